// round 7
// baseline (speedup 1.0000x reference)
#include <cuda_runtime.h>
#include <cstdint>

// ─────────────────────────────────────────────────────────────────────────────
// SecondOrderFeatureInteraction via mma.sync.m16n8k8.tf32 batched Gram.
//   out[b, pair(i,j)] = dot(x[b,i,:], x[b,j,:]), i<j.  B=8192, N=32, D=256.
// One warp owns one batch. KC=128 staging: 512B contiguous per row per stage
// (one cp.async per row; max HBM row-buffer locality), warp-private 2-stage
// pipeline, 32x32 gram in 24 accumulators. Gram symmetry: B-frags == A-frags.
// ─────────────────────────────────────────────────────────────────────────────

static constexpr int NF = 32, DD = 256, NPAIRS = 496;
static constexpr int BPC = 2;                     // batches per CTA (1/warp)
static constexpr int BLOCK = BPC * 32;            // 64 threads, 2 warps
static constexpr int KC = 128;                    // k-extent per stage
static constexpr int ROWB = KC * 4;               // 512 B per row per stage
static constexpr int STAGE_BYTES = BPC * NF * ROWB;      // 32 KB
static constexpr int NSTAGES = 2;
static constexpr int NKST = DD / KC;              // 2 k-stages

#define DI __device__ __forceinline__

DI uint32_t smem_u32(const void* p) {
    uint32_t a;
    asm("{ .reg .u64 t; cvta.to.shared.u64 t, %1; cvt.u32.u64 %0, t; }"
        : "=r"(a) : "l"(p));
    return a;
}

DI void cp_async16(uint32_t dst, const void* src) {
    asm volatile("cp.async.cg.shared.global [%0], [%1], 16;"
                 :: "r"(dst), "l"(src) : "memory");
}

DI float lds_f32(uint32_t a) {
    float v;
    asm volatile("ld.shared.f32 %0, [%1];" : "=f"(v) : "r"(a));
    return v;
}

DI uint32_t to_tf32(float f) {
    uint32_t r;
    asm("cvt.rna.tf32.f32 %0, %1;" : "=r"(r) : "f"(f));
    return r;
}

DI void mma_tf32(float* d, const uint32_t* a, uint32_t b0, uint32_t b1) {
    asm volatile(
        "mma.sync.aligned.m16n8k8.row.col.f32.tf32.tf32.f32 "
        "{%0,%1,%2,%3}, {%4,%5,%6,%7}, {%8,%9}, {%0,%1,%2,%3};"
        : "+f"(d[0]), "+f"(d[1]), "+f"(d[2]), "+f"(d[3])
        : "r"(a[0]), "r"(a[1]), "r"(a[2]), "r"(a[3]), "r"(b0), "r"(b1));
}

extern __shared__ char dynsmem[];

__global__ void __launch_bounds__(BLOCK, 3)
soi_mma_kernel(const float* __restrict__ x, float* __restrict__ out) {
    const uint32_t sb = smem_u32(dynsmem);
    const int lane = threadIdx.x & 31, wid = threadIdx.x >> 5;
    const long long batch0 = (long long)blockIdx.x * BPC;
    const float* xg = x + (batch0 + wid) * (NF * DD);   // warp's own batch

    // ── warp-private stage loader: 32 rows x 128 floats (16 KB).
    //    One cp.async per row: lane = 16B chunk, 512B contiguous = 4 lines.
    //    smem: row stride 512B, chunk index XOR-swizzled by (row&7) (low-3 bits).
    auto load_stage = [&](int ks) {
        const uint32_t buf = sb + (ks & 1) * STAGE_BYTES;
        #pragma unroll
        for (int row = 0; row < NF; row++) {
            const float* src = xg + (long long)row * DD + ks * KC + lane * 4;
            const uint32_t dst = buf + (uint32_t)(wid * NF + row) * ROWB
                               + (uint32_t)((lane ^ (row & 7)) << 4);
            cp_async16(dst, src);
        }
        asm volatile("cp.async.commit_group;" ::: "memory");
    };

    // ── fragment addressing ──
    const int r7 = lane >> 2;                     // row-in-8, swizzle key
    const uint32_t rowA = (uint32_t)(wid * NF + r7) * ROWB + (lane & 3) * 4;

    float acc[6][4];
    #pragma unroll
    for (int t = 0; t < 6; t++)
        #pragma unroll
        for (int e = 0; e < 4; e++) acc[t][e] = 0.f;

    load_stage(0);

    for (int ks = 0; ks < NKST; ks++) {
        if (ks + 1 < NKST) {
            load_stage(ks + 1);
            asm volatile("cp.async.wait_group 1;" ::: "memory");
        } else {
            asm volatile("cp.async.wait_group 0;" ::: "memory");
        }
        __syncwarp();                              // warp-private buffers only

        const uint32_t base = sb + (ks & 1) * STAGE_BYTES + rowA;
        #pragma unroll
        for (int kq = 0; kq < KC / 8; kq++) {      // 16 k-quads per stage
            const uint32_t o0 = (uint32_t)(((2 * kq + 0) ^ r7) << 4);
            const uint32_t o1 = (uint32_t)(((2 * kq + 1) ^ r7) << 4);
            uint32_t a[8];
            a[0] = to_tf32(lds_f32(base + o0));            // rows 0-7,  k lo
            a[1] = to_tf32(lds_f32(base + 4096 + o0));     // rows 8-15, k lo
            a[2] = to_tf32(lds_f32(base + o1));            // rows 0-7,  k hi
            a[3] = to_tf32(lds_f32(base + 4096 + o1));     // rows 8-15, k hi
            a[4] = to_tf32(lds_f32(base + 8192 + o0));     // rows 16-23, k lo
            a[5] = to_tf32(lds_f32(base + 12288 + o0));    // rows 24-31, k lo
            a[6] = to_tf32(lds_f32(base + 8192 + o1));     // rows 16-23, k hi
            a[7] = to_tf32(lds_f32(base + 12288 + o1));    // rows 24-31, k hi
            // Gram: b-fragments are the a-fragment registers (row.col, B=A^T)
            mma_tf32(acc[0], a + 0, a[0], a[2]);   // (m0, n0)
            mma_tf32(acc[1], a + 0, a[1], a[3]);   // (m0, n1)
            mma_tf32(acc[2], a + 0, a[4], a[6]);   // (m0, n2)
            mma_tf32(acc[3], a + 0, a[5], a[7]);   // (m0, n3)
            mma_tf32(acc[4], a + 4, a[4], a[6]);   // (m1, n2)
            mma_tf32(acc[5], a + 4, a[5], a[7]);   // (m1, n3)
        }
        __syncwarp();                              // reads done before refill
    }

    // ── epilogue: scatter the strict upper triangle ──
    static const int IOFF[6] = { 0, 0, 0, 0, 16, 16 };
    static const int JOFF[6] = { 0, 8, 16, 24, 16, 24 };
    float* ob = out + (batch0 + wid) * NPAIRS;
    const int ib = lane >> 2, jb = 2 * (lane & 3);
    #pragma unroll
    for (int t = 0; t < 6; t++) {
        #pragma unroll
        for (int e = 0; e < 4; e++) {
            const int i = IOFF[t] + ib + 8 * (e >> 1);
            const int j = JOFF[t] + jb + (e & 1);
            if (j > i)
                ob[i * 31 - (i * (i - 1)) / 2 + (j - i - 1)] = acc[t][e];
        }
    }
}

extern "C" void kernel_launch(void* const* d_in, const int* in_sizes, int n_in,
                              void* d_out, int out_size) {
    const float* x = (const float*)d_in[0];
    float* out = (float*)d_out;
    const int nb = in_sizes[0] / (NF * DD);        // 8192
    cudaFuncSetAttribute(soi_mma_kernel,
                         cudaFuncAttributeMaxDynamicSharedMemorySize,
                         NSTAGES * STAGE_BYTES);
    soi_mma_kernel<<<nb / BPC, BLOCK, NSTAGES * STAGE_BYTES>>>(x, out);
}

// round 10
// speedup vs baseline: 1.0054x; 1.0054x over previous
#include <cuda_runtime.h>
#include <cstdint>

// ─────────────────────────────────────────────────────────────────────────────
// SecondOrderFeatureInteraction via mma.sync.m16n8k8.tf32 batched Gram.
//   out[b, pair(i,j)] = dot(x[b,i,:], x[b,j,:]), i<j.  B=8192, N=32, D=256.
// One warp owns one batch. KC=128 staging (512B contiguous per row per stage),
// warp-private 2-stage cp.async pipeline, 32x32 gram in 24 accumulators.
// Gram symmetry: B-fragments == A-fragments. Epilogue stages the 496-float
// triangle in the warp's OWN stage-0 slice (race-free) and emits coalesced
// STG.128 (minimal LTS store sectors).
// ─────────────────────────────────────────────────────────────────────────────

static constexpr int NF = 32, DD = 256, NPAIRS = 496;
static constexpr int BPC = 2;                     // batches per CTA (1/warp)
static constexpr int BLOCK = BPC * 32;            // 64 threads, 2 warps
static constexpr int KC = 128;                    // k-extent per stage
static constexpr int ROWB = KC * 4;               // 512 B per row per stage
static constexpr int STAGE_BYTES = BPC * NF * ROWB;      // 32 KB
static constexpr int NSTAGES = 2;
static constexpr int NKST = DD / KC;              // 2 k-stages

#define DI __device__ __forceinline__

DI uint32_t smem_u32(const void* p) {
    uint32_t a;
    asm("{ .reg .u64 t; cvta.to.shared.u64 t, %1; cvt.u32.u64 %0, t; }"
        : "=r"(a) : "l"(p));
    return a;
}

DI void cp_async16(uint32_t dst, const void* src) {
    asm volatile("cp.async.cg.shared.global [%0], [%1], 16;"
                 :: "r"(dst), "l"(src) : "memory");
}

DI float lds_f32(uint32_t a) {
    float v;
    asm volatile("ld.shared.f32 %0, [%1];" : "=f"(v) : "r"(a));
    return v;
}

DI void sts_f32(uint32_t a, float v) {
    asm volatile("st.shared.f32 [%0], %1;" :: "r"(a), "f"(v) : "memory");
}

DI uint32_t to_tf32(float f) {
    uint32_t r;
    asm("cvt.rna.tf32.f32 %0, %1;" : "=r"(r) : "f"(f));
    return r;
}

DI void mma_tf32(float* d, const uint32_t* a, uint32_t b0, uint32_t b1) {
    asm volatile(
        "mma.sync.aligned.m16n8k8.row.col.f32.tf32.tf32.f32 "
        "{%0,%1,%2,%3}, {%4,%5,%6,%7}, {%8,%9}, {%0,%1,%2,%3};"
        : "+f"(d[0]), "+f"(d[1]), "+f"(d[2]), "+f"(d[3])
        : "r"(a[0]), "r"(a[1]), "r"(a[2]), "r"(a[3]), "r"(b0), "r"(b1));
}

extern __shared__ char dynsmem[];

__global__ void __launch_bounds__(BLOCK, 3)
soi_mma_kernel(const float* __restrict__ x, float* __restrict__ out) {
    const uint32_t sb = smem_u32(dynsmem);
    const int lane = threadIdx.x & 31, wid = threadIdx.x >> 5;
    const long long batch0 = (long long)blockIdx.x * BPC;
    const float* xg = x + (batch0 + wid) * (NF * DD);   // warp's own batch

    // ── warp-private stage loader: 32 rows x 128 floats (16 KB).
    //    One cp.async per row: lane = 16B chunk, 512B contiguous = 4 lines.
    //    smem: row stride 512B, chunk index XOR-swizzled by (row&7).
    auto load_stage = [&](int ks) {
        const uint32_t buf = sb + (ks & 1) * STAGE_BYTES;
        #pragma unroll
        for (int row = 0; row < NF; row++) {
            const float* src = xg + (long long)row * DD + ks * KC + lane * 4;
            const uint32_t dst = buf + (uint32_t)(wid * NF + row) * ROWB
                               + (uint32_t)((lane ^ (row & 7)) << 4);
            cp_async16(dst, src);
        }
        asm volatile("cp.async.commit_group;" ::: "memory");
    };

    // ── fragment addressing ──
    const int r7 = lane >> 2;                     // row-in-8, swizzle key
    const uint32_t rowA = (uint32_t)(wid * NF + r7) * ROWB + (lane & 3) * 4;

    float acc[6][4];
    #pragma unroll
    for (int t = 0; t < 6; t++)
        #pragma unroll
        for (int e = 0; e < 4; e++) acc[t][e] = 0.f;

    load_stage(0);

    for (int ks = 0; ks < NKST; ks++) {
        if (ks + 1 < NKST) {
            load_stage(ks + 1);
            asm volatile("cp.async.wait_group 1;" ::: "memory");
        } else {
            asm volatile("cp.async.wait_group 0;" ::: "memory");
        }
        __syncwarp();                              // warp-private buffers only

        const uint32_t base = sb + (ks & 1) * STAGE_BYTES + rowA;
        #pragma unroll
        for (int kq = 0; kq < KC / 8; kq++) {      // 16 k-quads per stage
            const uint32_t o0 = (uint32_t)(((2 * kq + 0) ^ r7) << 4);
            const uint32_t o1 = (uint32_t)(((2 * kq + 1) ^ r7) << 4);
            uint32_t a[8];
            a[0] = to_tf32(lds_f32(base + o0));            // rows 0-7,  k lo
            a[1] = to_tf32(lds_f32(base + 4096 + o0));     // rows 8-15, k lo
            a[2] = to_tf32(lds_f32(base + o1));            // rows 0-7,  k hi
            a[3] = to_tf32(lds_f32(base + 4096 + o1));     // rows 8-15, k hi
            a[4] = to_tf32(lds_f32(base + 8192 + o0));     // rows 16-23, k lo
            a[5] = to_tf32(lds_f32(base + 12288 + o0));    // rows 24-31, k lo
            a[6] = to_tf32(lds_f32(base + 8192 + o1));     // rows 16-23, k hi
            a[7] = to_tf32(lds_f32(base + 12288 + o1));    // rows 24-31, k hi
            // Gram: b-fragments are the a-fragment registers (row.col, B=A^T)
            mma_tf32(acc[0], a + 0, a[0], a[2]);   // (m0, n0)
            mma_tf32(acc[1], a + 0, a[1], a[3]);   // (m0, n1)
            mma_tf32(acc[2], a + 0, a[4], a[6]);   // (m0, n2)
            mma_tf32(acc[3], a + 0, a[5], a[7]);   // (m0, n3)
            mma_tf32(acc[4], a + 4, a[4], a[6]);   // (m1, n2)
            mma_tf32(acc[5], a + 4, a[5], a[7]);   // (m1, n3)
        }
        __syncwarp();                              // reads done before refill
    }

    // ── epilogue: scatter triangle into the warp's OWN stage-0 slice (this
    //    warp finished reading it; no other warp ever touches it), then emit
    //    as coalesced STG.128 — 62 store sectors per warp (minimum). ──
    static const int IOFF[6] = { 0, 0, 0, 0, 16, 16 };
    static const int JOFF[6] = { 0, 8, 16, 24, 16, 24 };
    const uint32_t eb = sb + (uint32_t)(wid * NF) * ROWB;   // warp-private 16KB slab
    const int ib = lane >> 2, jb = 2 * (lane & 3);
    #pragma unroll
    for (int t = 0; t < 6; t++) {
        #pragma unroll
        for (int e = 0; e < 4; e++) {
            const int i = IOFF[t] + ib + 8 * (e >> 1);
            const int j = JOFF[t] + jb + (e & 1);
            if (j > i)
                sts_f32(eb + (uint32_t)(i * 31 - (i * (i - 1)) / 2 + (j - i - 1)) * 4,
                        acc[t][e]);
        }
    }
    __syncwarp();
    float4* ob4 = reinterpret_cast<float4*>(out + (batch0 + wid) * NPAIRS);
    #pragma unroll
    for (int q = 0; q < 4; q++) {
        const int idx = q * 32 + lane;
        if (idx < NPAIRS / 4) {                    // 124 float4 = 1984 B
            float4 v;
            asm volatile("ld.shared.v4.f32 {%0,%1,%2,%3}, [%4];"
                         : "=f"(v.x), "=f"(v.y), "=f"(v.z), "=f"(v.w)
                         : "r"(eb + (uint32_t)idx * 16));
            ob4[idx] = v;
        }
    }
}

extern "C" void kernel_launch(void* const* d_in, const int* in_sizes, int n_in,
                              void* d_out, int out_size) {
    const float* x = (const float*)d_in[0];
    float* out = (float*)d_out;
    const int nb = in_sizes[0] / (NF * DD);        // 8192
    cudaFuncSetAttribute(soi_mma_kernel,
                         cudaFuncAttributeMaxDynamicSharedMemorySize,
                         NSTAGES * STAGE_BYTES);
    soi_mma_kernel<<<nb / BPC, BLOCK, NSTAGES * STAGE_BYTES>>>(x, out);
}